// round 13
// baseline (speedup 1.0000x reference)
#include <cuda_runtime.h>
#include <cuda_bf16.h>
#include <math.h>
#include <stdint.h>

// Problem dims (fixed)
#define Bb 64
#define Tt 128
#define Ff 2048
#define Hh 1024
#define Cc 22
#define G4 4096   // 4*H
#define NB 128    // persistent grid size
#define MT 8192   // Bb*Tt

// ---------------- scratch (device globals) ----------------
__device__ float g_enc_xw[(size_t)MT*G4];
__device__ float g_dec_xw[(size_t)MT*G4];
__device__ float g_proj[(size_t)MT*Hh];
__device__ float g_c1[Bb*Hh], g_c2[Bb*Hh];
__device__ float g_h2f[2][Bb*Hh];
__device__ __nv_bfloat16 g_hhi[2][Bb*Hh], g_hlo[2][Bb*Hh];
__device__ __nv_bfloat16 g_h2hi[2][Bb*Hh], g_h2lo[2][Bb*Hh];
__device__ __nv_bfloat16 g_attnhi[Bb*Hh], g_attnlo[Bb*Hh];
__device__ float g_logits[Bb*Tt];
__device__ float g_Wd_h [(size_t)G4*Hh];
__device__ float g_Wfused[(size_t)G4*Hh];
__device__ float g_be[G4], g_bd[G4], g_bf[G4];
__device__ float g_zero[Hh];
__device__ unsigned g_barcnt, g_bargen;
// bf16 hi/lo operands
__device__ __nv_bfloat16 g_xhi[(size_t)MT*Ff],  g_xlo[(size_t)MT*Ff];
__device__ __nv_bfloat16 g_Wehi[(size_t)G4*Ff], g_Welo[(size_t)G4*Ff];
__device__ __nv_bfloat16 g_Wdhi[(size_t)G4*Ff], g_Wdlo[(size_t)G4*Ff];
__device__ __nv_bfloat16 g_htshi[(size_t)MT*Hh], g_htslo[(size_t)MT*Hh];
__device__ __nv_bfloat16 g_We2dhi[(size_t)Hh*Hh], g_We2dlo[(size_t)Hh*Hh];
__device__ __nv_bfloat16 g_Whhehi[(size_t)G4*Hh], g_Whhelo[(size_t)G4*Hh];
__device__ __nv_bfloat16 g_Wfhi[(size_t)G4*Hh],   g_Wflo[(size_t)G4*Hh];
__device__ __nv_bfloat16 g_Whhdhi[(size_t)G4*Hh], g_Whhdlo[(size_t)G4*Hh];
__device__ __nv_bfloat16 g_Wdhhi[(size_t)G4*Hh],  g_Wdhlo[(size_t)G4*Hh];
__device__ __nv_bfloat16 g_Wd2eThi[(size_t)Hh*Hh], g_Wd2eTlo[(size_t)Hh*Hh];

__device__ __forceinline__ uint32_t smem_u32(const void* p)
{
    uint32_t a;
    asm("{ .reg .u64 t; cvta.to.shared.u64 t, %1; cvt.u32.u64 %0, t; }" : "=r"(a) : "l"(p));
    return a;
}

// ---------------- mma.sync helpers ----------------
__device__ __forceinline__ void ldmx4(uint32_t* r, uint32_t addr)
{
    asm volatile("ldmatrix.sync.aligned.m8n8.x4.shared.b16 {%0,%1,%2,%3}, [%4];"
        : "=r"(r[0]), "=r"(r[1]), "=r"(r[2]), "=r"(r[3]) : "r"(addr));
}
__device__ __forceinline__ void ldmx2(uint32_t* r, uint32_t addr)
{
    asm volatile("ldmatrix.sync.aligned.m8n8.x2.shared.b16 {%0,%1}, [%2];"
        : "=r"(r[0]), "=r"(r[1]) : "r"(addr));
}
__device__ __forceinline__ void mma16816(float* c, const uint32_t* a, uint32_t b0, uint32_t b1)
{
    asm volatile(
        "mma.sync.aligned.m16n8k16.row.col.f32.bf16.bf16.f32 "
        "{%0,%1,%2,%3}, {%4,%5,%6,%7}, {%8,%9}, {%0,%1,%2,%3};"
        : "+f"(c[0]), "+f"(c[1]), "+f"(c[2]), "+f"(c[3])
        : "r"(a[0]), "r"(a[1]), "r"(a[2]), "r"(a[3]), "r"(b0), "r"(b1));
}
__device__ __forceinline__ void cpa16(uint32_t d, const void* s)
{
    asm volatile("cp.async.cg.shared.global [%0], [%1], 16;" :: "r"(d), "l"(s));
}
#define CP_COMMIT() asm volatile("cp.async.commit_group;")
#define CP_WAIT0()  asm volatile("cp.async.wait_group 0;")
#define CP_WAIT1()  asm volatile("cp.async.wait_group 1;")

// ---------------- flat grid barrier (R10, measured-good) ----------------
__device__ __forceinline__ void gbar()
{
    __syncthreads();
    if (threadIdx.x == 0) {
        __threadfence();
        unsigned gen = *(volatile unsigned*)&g_bargen;
        if (atomicAdd(&g_barcnt, 1u) == NB - 1u) {
            g_barcnt = 0u;
            __threadfence();
            atomicAdd(&g_bargen, 1u);
        } else {
            while (*(volatile unsigned*)&g_bargen == gen) { }
        }
        __threadfence();
    }
    __syncthreads();
}

__device__ __forceinline__ float sigm(float x) { return 1.f / (1.f + expf(-x)); }
__device__ __forceinline__ float wred(float s)
{
#pragma unroll
    for (int o = 16; o; o >>= 1) s += __shfl_down_sync(0xffffffffu, s, o);
    return s;
}

// ================= setup kernels (R10, measured-good) =================
__global__ void perm_w_kernel(float* dst, const float* src, int ldsrc, int K)
{
    int r = blockIdx.x;
    int g = r >> 10, j = r & 1023;
    int p = 4 * j + g;
    const float* s = src + (size_t)r * ldsrc;
    float*       d = dst + (size_t)p * K;
    for (int k = threadIdx.x * 4; k < K; k += blockDim.x * 4)
        *(float4*)(d + k) = *(const float4*)(s + k);
}

__global__ void perm_w_hilo_kernel(__nv_bfloat16* hi, __nv_bfloat16* lo,
                                   const float* src, int ldsrc, int K)
{
    int r = blockIdx.x;
    int g = r >> 10, j = r & 1023;
    int p = 4 * j + g;
    const float* s = src + (size_t)r * ldsrc;
    __nv_bfloat16* dh = hi + (size_t)p * K;
    __nv_bfloat16* dl = lo + (size_t)p * K;
    for (int k = threadIdx.x * 4; k < K; k += blockDim.x * 4) {
        float4 v = *(const float4*)(s + k);
        __nv_bfloat162 h01, h23, l01, l23;
        h01.x = __float2bfloat16(v.x); h01.y = __float2bfloat16(v.y);
        h23.x = __float2bfloat16(v.z); h23.y = __float2bfloat16(v.w);
        l01.x = __float2bfloat16(v.x - __bfloat162float(h01.x));
        l01.y = __float2bfloat16(v.y - __bfloat162float(h01.y));
        l23.x = __float2bfloat16(v.z - __bfloat162float(h23.x));
        l23.y = __float2bfloat16(v.w - __bfloat162float(h23.y));
        *(__nv_bfloat162*)(dh + k)     = h01;
        *(__nv_bfloat162*)(dh + k + 2) = h23;
        *(__nv_bfloat162*)(dl + k)     = l01;
        *(__nv_bfloat162*)(dl + k + 2) = l23;
    }
}

__global__ void transp_hilo_kernel(const float* __restrict__ src,
                                   __nv_bfloat16* __restrict__ hi,
                                   __nv_bfloat16* __restrict__ lo)
{
    __shared__ float tile[32][33];
    int bx = blockIdx.x * 32, by = blockIdx.y * 32;
    int tx = threadIdx.x, ty = threadIdx.y;
#pragma unroll
    for (int i = 0; i < 32; i += 8)
        tile[ty + i][tx] = src[(size_t)(by + ty + i) * Hh + bx + tx];
    __syncthreads();
#pragma unroll
    for (int i = 0; i < 32; i += 8) {
        float v = tile[tx][ty + i];
        __nv_bfloat16 h = __float2bfloat16(v);
        size_t o = (size_t)(bx + ty + i) * Hh + by + tx;
        hi[o] = h;
        lo[o] = __float2bfloat16(v - __bfloat162float(h));
    }
}

__global__ void perm_b_kernel(const float* ebi, const float* ebh,
                              const float* dbi, const float* dbh)
{
    int r = blockIdx.x * blockDim.x + threadIdx.x;
    if (r < G4) {
        int g = r >> 10, j = r & 1023, p = 4 * j + g;
        g_be[p] = ebi[r] + ebh[r];
        g_bd[p] = dbi[r] + dbh[r];
    }
}

__global__ void bfused_kernel(const float* __restrict__ bd2e)
{
    int p = blockIdx.x;
    const float* w = g_Wd_h + (size_t)p * Hh;
    float s = 0.f;
    for (int k = threadIdx.x; k < Hh; k += 32) s += w[k] * bd2e[k];
    s = wred(s);
    if (threadIdx.x == 0) g_bf[p] = s;
}

__global__ void zero_kernel()
{
    int i = blockIdx.x * blockDim.x + threadIdx.x;
    if (i < Bb * Hh) {
        g_c1[i] = 0.f; g_c2[i] = 0.f;
        g_h2f[0][i] = 0.f; g_h2f[1][i] = 0.f;
        __nv_bfloat16 z = __float2bfloat16(0.f);
        g_hhi[0][i] = z; g_hlo[0][i] = z;
        g_hhi[1][i] = z; g_hlo[1][i] = z;
        g_h2hi[0][i] = z; g_h2lo[0][i] = z;
        g_h2hi[1][i] = z; g_h2lo[1][i] = z;
    }
    if (i == 0) g_barcnt = 0u;
}

__global__ void conv_hilo(const float* __restrict__ in, __nv_bfloat16* __restrict__ hi,
                          __nv_bfloat16* __restrict__ lo, int n4)
{
    int i = blockIdx.x * blockDim.x + threadIdx.x;
    if (i < n4) {
        float4 v = ((const float4*)in)[i];
        __nv_bfloat162 h01, h23, l01, l23;
        h01.x = __float2bfloat16(v.x); h01.y = __float2bfloat16(v.y);
        h23.x = __float2bfloat16(v.z); h23.y = __float2bfloat16(v.w);
        l01.x = __float2bfloat16(v.x - __bfloat162float(h01.x));
        l01.y = __float2bfloat16(v.y - __bfloat162float(h01.y));
        l23.x = __float2bfloat16(v.z - __bfloat162float(h23.x));
        l23.y = __float2bfloat16(v.w - __bfloat162float(h23.y));
        ((__nv_bfloat162*)hi)[i * 2]     = h01;
        ((__nv_bfloat162*)hi)[i * 2 + 1] = h23;
        ((__nv_bfloat162*)lo)[i * 2]     = l01;
        ((__nv_bfloat162*)lo)[i * 2 + 1] = l23;
    }
}

// ================= mma.sync bf16 split-precision GEMM — BK=64 staging ===========
// C[M,N] = (Ahi+Alo)[M,K] @ (Bhi+Blo)[N,K]^T + bias   (hi*hi + hi*lo + lo*hi)
// CTA tile 128x64, BK=64 per stage, 8 warps (4Mx2N), warp tile 32x32.
// smem rows padded to 72 bf16 (144B stride -> conflict-free, same as scans).
#define PAD2 72
#define SA2   (128 * PAD2 * 2)                  // 18432 B (one of hi/lo)
#define SB2   (64 * PAD2 * 2)                   // 9216 B
#define STG2  (2 * SA2 + 2 * SB2)               // 55296 B
#define MM_SMEM (2 * STG2)                      // 110592 B

__global__ __launch_bounds__(256)
void mma_gemm(const __nv_bfloat16* __restrict__ Ahi, const __nv_bfloat16* __restrict__ Alo,
              const __nv_bfloat16* __restrict__ Bhi, const __nv_bfloat16* __restrict__ Blo,
              const float* __restrict__ bias, float* __restrict__ C, int ldc, int K)
{
    extern __shared__ char smem[];
    const uint32_t sb = smem_u32(smem);
    const int tid = threadIdx.x;
    const int wid = tid >> 5, lane = tid & 31;
    const int wm = wid & 3, wn = wid >> 2;
    const int m0 = blockIdx.y * 128, n0 = blockIdx.x * 64;

    float acc[2][4][4];
#pragma unroll
    for (int i = 0; i < 2; i++)
#pragma unroll
        for (int j = 0; j < 4; j++)
#pragma unroll
            for (int q = 0; q < 4; q++) acc[i][j][q] = 0.f;

    // load slots: A row = tid>>1 (128 rows), 4 of 8 16B-segments per thread
    const int arow = tid >> 1, ahalf = (tid & 1) * 4;
    // B row = tid>>2 (64 rows), 2 of 8 segments per thread
    const int brow = tid >> 2, bhalf = (tid & 3) * 2;
    const int S = K >> 6;
    const int lmat = lane >> 3, lr = lane & 7;
    const uint32_t a_off0 = (uint32_t)(((wm * 32 + (lmat & 1) * 8 + lr) * PAD2 + (lmat >> 1) * 8) * 2);
    const uint32_t b_off0 = (uint32_t)(((wn * 32 + (lmat & 1) * 8 + lr) * PAD2 + (lmat >> 1) * 8) * 2);

#define LOAD_STAGE(buf, kb)                                                        \
    do {                                                                           \
        uint32_t st = sb + (buf) * STG2;                                           \
        const __nv_bfloat16* gAh = Ahi + (size_t)(m0 + arow) * K + (kb);           \
        const __nv_bfloat16* gAl = Alo + (size_t)(m0 + arow) * K + (kb);           \
        uint32_t dA = st + (uint32_t)(arow * PAD2 * 2);                            \
        _Pragma("unroll")                                                          \
        for (int i_ = 0; i_ < 4; i_++) {                                           \
            int sg = ahalf + i_;                                                   \
            cpa16(dA + sg * 16, gAh + sg * 8);                                     \
            cpa16(dA + SA2 + sg * 16, gAl + sg * 8);                               \
        }                                                                          \
        const __nv_bfloat16* gBh = Bhi + (size_t)(n0 + brow) * K + (kb);           \
        const __nv_bfloat16* gBl = Blo + (size_t)(n0 + brow) * K + (kb);           \
        uint32_t dB = st + 2 * SA2 + (uint32_t)(brow * PAD2 * 2);                  \
        _Pragma("unroll")                                                          \
        for (int i_ = 0; i_ < 2; i_++) {                                           \
            int sg = bhalf + i_;                                                   \
            cpa16(dB + sg * 16, gBh + sg * 8);                                     \
            cpa16(dB + SB2 + sg * 16, gBl + sg * 8);                               \
        }                                                                          \
    } while (0)

    LOAD_STAGE(0, 0);
    CP_COMMIT();

    for (int s = 0; s < S; s++) {
        if (s + 1 < S) {
            LOAD_STAGE((s + 1) & 1, (s + 1) * 64);
            CP_COMMIT();
            CP_WAIT1();
        } else {
            CP_WAIT0();
        }
        __syncthreads();

        const uint32_t st = sb + (s & 1) * STG2;
#pragma unroll
        for (int kk = 0; kk < 4; kk++) {       // four k16 steps per stage
            const uint32_t kadd = (uint32_t)(kk * 16 * 2);
            uint32_t ah[2][4], al[2][4];
#pragma unroll
            for (int mf = 0; mf < 2; mf++) {
                uint32_t aaddr = st + a_off0 + (uint32_t)(mf * 16 * PAD2 * 2) + kadd;
                ldmx4(ah[mf], aaddr);
                ldmx4(al[mf], aaddr + SA2);
            }
            uint32_t bh[2][4], bl[2][4];
#pragma unroll
            for (int nf2 = 0; nf2 < 2; nf2++) {
                uint32_t baddr = st + 2 * SA2 + b_off0 + (uint32_t)(nf2 * 16 * PAD2 * 2) + kadd;
                ldmx4(bh[nf2], baddr);
                ldmx4(bl[nf2], baddr + SB2);
            }
#pragma unroll
            for (int mf = 0; mf < 2; mf++)
#pragma unroll
                for (int nf2 = 0; nf2 < 2; nf2++) {
                    mma16816(acc[mf][nf2 * 2 + 0], ah[mf], bh[nf2][0], bh[nf2][2]);
                    mma16816(acc[mf][nf2 * 2 + 0], ah[mf], bl[nf2][0], bl[nf2][2]);
                    mma16816(acc[mf][nf2 * 2 + 0], al[mf], bh[nf2][0], bh[nf2][2]);
                    mma16816(acc[mf][nf2 * 2 + 1], ah[mf], bh[nf2][1], bh[nf2][3]);
                    mma16816(acc[mf][nf2 * 2 + 1], ah[mf], bl[nf2][1], bl[nf2][3]);
                    mma16816(acc[mf][nf2 * 2 + 1], al[mf], bh[nf2][1], bh[nf2][3]);
                }
        }
        __syncthreads();
    }

    const int mrow = m0 + wm * 32 + (lane >> 2);
    const int ncol = n0 + wn * 32 + (lane & 3) * 2;
#pragma unroll
    for (int mf = 0; mf < 2; mf++)
#pragma unroll
        for (int nf = 0; nf < 4; nf++) {
            int r = mrow + mf * 16;
            int c = ncol + nf * 8;
            float2 b2 = *(const float2*)(bias + c);
            *(float2*)(C + (size_t)r * ldc + c) =
                make_float2(acc[mf][nf][0] + b2.x, acc[mf][nf][1] + b2.y);
            *(float2*)(C + (size_t)(r + 8) * ldc + c) =
                make_float2(acc[mf][nf][2] + b2.x, acc[mf][nf][3] + b2.y);
        }
#undef LOAD_STAGE
}

// ================= persistent encoder scan (R10 verbatim) =======================
#define EKC 64
#define EPITCH 144
#define E_A_PL (64 * EPITCH)
#define E_W_PL (32 * EPITCH)
#define E_STAGE (2 * E_A_PL + 2 * E_W_PL)
#define E_SMEM  (2 * E_STAGE + 8192)

__global__ __launch_bounds__(512)
void enc_scan()
{
    extern __shared__ char smc[];
    const uint32_t sb = smem_u32(smc);
    const int tid = threadIdx.x, bi = blockIdx.x;
    const int wid = tid >> 5, lane = tid & 31;
    const int wm = wid & 3, wn = wid >> 2;
    const int n0 = bi * 32;
    const int lmat = lane >> 3, lr = lane & 7;
    const uint32_t a_loff = (uint32_t)((wm * 16 + (lmat & 1) * 8 + lr) * EPITCH + (lmat >> 1) * 16);
    const uint32_t b_loff = (uint32_t)((wn * 8 + (lane & 7)) * EPITCH + ((lane & 15) >> 3) * 16);
    float* P = (float*)(smc + 2 * E_STAGE);
    const int ar = tid >> 3, asg = tid & 7;
    const int wpl = tid >> 8, wr = (tid >> 3) & 31, wsg = tid & 7;

#define E_LOAD(bf, kc) do {                                                       \
    uint32_t st = sb + (bf) * E_STAGE;                                            \
    int kcc = (kc) * EKC;                                                         \
    cpa16(st + ar * EPITCH + asg * 16,          Ahi + ar * Hh + kcc + asg * 8);   \
    cpa16(st + E_A_PL + ar * EPITCH + asg * 16, Alo + ar * Hh + kcc + asg * 8);   \
    const __nv_bfloat16* ws = wpl ? g_Whhelo : g_Whhehi;                          \
    cpa16(st + 2 * E_A_PL + wpl * E_W_PL + wr * EPITCH + wsg * 16,                \
          ws + (size_t)(n0 + wr) * Hh + kcc + wsg * 8);                           \
} while (0)

    for (int t = 0; t < Tt; t++) {
        const __nv_bfloat16* Ahi = g_hhi[t & 1];
        const __nv_bfloat16* Alo = g_hlo[t & 1];

        float acc[4] = {0.f, 0.f, 0.f, 0.f};
        E_LOAD(0, 0);
        CP_COMMIT();
        for (int kc = 0; kc < 16; kc++) {
            if (kc < 15) {
                E_LOAD((kc + 1) & 1, kc + 1);
                CP_COMMIT();
                CP_WAIT1();
            } else {
                CP_WAIT0();
            }
            __syncthreads();
            uint32_t st = sb + (kc & 1) * E_STAGE;
#pragma unroll
            for (int kk = 0; kk < 4; kk++) {
                uint32_t ka = (uint32_t)(kk * 32);
                uint32_t ahi[4], alo[4], bh[2], bl[2];
                ldmx4(ahi, st + a_loff + ka);
                ldmx4(alo, st + E_A_PL + a_loff + ka);
                ldmx2(bh, st + 2 * E_A_PL + b_loff + ka);
                ldmx2(bl, st + 2 * E_A_PL + E_W_PL + b_loff + ka);
                mma16816(acc, ahi, bh[0], bh[1]);
                mma16816(acc, ahi, bl[0], bl[1]);
                mma16816(acc, alo, bh[0], bh[1]);
            }
            __syncthreads();
        }
        {   // store partials
            int row = wm * 16 + (lane >> 2), col = wn * 8 + (lane & 3) * 2;
            P[row * 32 + col] = acc[0];       P[row * 32 + col + 1] = acc[1];
            P[(row + 8) * 32 + col] = acc[2]; P[(row + 8) * 32 + col + 1] = acc[3];
        }
        __syncthreads();
        {   // fused LSTM cell
            int b = tid >> 3, jj = tid & 7, j = bi * 8 + jj;
            float4 x4 = *(const float4*)(g_enc_xw + ((size_t)b * Tt + t) * G4 + n0 + 4 * jj);
            int base = b * 32 + 4 * jj;
            float vi = P[base + 0] + x4.x;
            float vf = P[base + 1] + x4.y;
            float vg = P[base + 2] + x4.z;
            float vo = P[base + 3] + x4.w;
            float cn = sigm(vf) * g_c1[b * Hh + j] + sigm(vi) * tanhf(vg);
            float hn = sigm(vo) * tanhf(cn);
            g_c1[b * Hh + j] = cn;
            __nv_bfloat16 hh = __float2bfloat16(hn);
            __nv_bfloat16 hl = __float2bfloat16(hn - __bfloat162float(hh));
            g_hhi[(t + 1) & 1][b * Hh + j] = hh;
            g_hlo[(t + 1) & 1][b * Hh + j] = hl;
            g_htshi[((size_t)b * Tt + t) * Hh + j] = hh;
            g_htslo[((size_t)b * Tt + t) * Hh + j] = hl;
        }
        gbar();
    }
#undef E_LOAD
}

// ================= persistent decoder scan (R10 verbatim: 3 barriers/step) ======
#define D_A_PL (64 * EPITCH)
#define D_W_PL (32 * EPITCH)
#define D_STAGE (4 * D_A_PL + 4 * D_W_PL)
#define D_SMEM  (2 * D_STAGE + 16384)

__global__ __launch_bounds__(512)
void dec_scan(const float* __restrict__ Wc, const float* __restrict__ bc,
              float* __restrict__ scores, float* __restrict__ aw_out)
{
    extern __shared__ char smc[];
    const uint32_t sb = smem_u32(smc);
    float* sm = (float*)smc;
    const int tid = threadIdx.x, bi = blockIdx.x;
    const int wid = tid >> 5, lane = tid & 31;
    const int warp = wid;
    const int b2 = bi >> 1;
    const int n0 = bi * 32;
    const int grp = wid >> 3, wg = wid & 7;
    const int wm = wg & 3, wn = wg >> 2;
    const int lmat = lane >> 3, lr = lane & 7;
    const uint32_t a_loff = (uint32_t)((wm * 16 + (lmat & 1) * 8 + lr) * EPITCH + (lmat >> 1) * 16)
                          + (uint32_t)(grp * 2 * D_A_PL);
    const uint32_t b_loff = (uint32_t)((wn * 16 + (lmat & 1) * 8 + lr) * EPITCH + (lmat >> 1) * 16)
                          + (uint32_t)(4 * D_A_PL + grp * 2 * D_W_PL);
    float* P = (float*)(smc + 2 * D_STAGE);
    const int ar = tid >> 3, asg = tid & 7;
    const int wpl = tid >> 8, wr = (tid >> 3) & 31, wsg = tid & 7;

#define D_LOAD(bf, kc) do {                                                       \
    uint32_t st = sb + (bf) * D_STAGE;                                            \
    int kcc = (kc) * EKC;                                                         \
    cpa16(st + 0 * D_A_PL + ar * EPITCH + asg * 16, g_attnhi + ar * Hh + kcc + asg * 8); \
    cpa16(st + 1 * D_A_PL + ar * EPITCH + asg * 16, g_attnlo + ar * Hh + kcc + asg * 8); \
    cpa16(st + 2 * D_A_PL + ar * EPITCH + asg * 16, h2hi + ar * Hh + kcc + asg * 8);     \
    cpa16(st + 3 * D_A_PL + ar * EPITCH + asg * 16, h2lo + ar * Hh + kcc + asg * 8);     \
    const __nv_bfloat16* w0s = wpl ? g_Wflo : g_Wfhi;                             \
    cpa16(st + 4 * D_A_PL + wpl * D_W_PL + wr * EPITCH + wsg * 16,                \
          w0s + (size_t)(n0 + wr) * Hh + kcc + wsg * 8);                          \
    const __nv_bfloat16* w1s = wpl ? g_Whhdlo : g_Whhdhi;                         \
    cpa16(st + 4 * D_A_PL + (2 + wpl) * D_W_PL + wr * EPITCH + wsg * 16,          \
          w1s + (size_t)(n0 + wr) * Hh + kcc + wsg * 8);                          \
} while (0)

    for (int t = 0; t < Tt; t++) {
        const float* h2cur = g_h2f[t & 1];

        // ---- A: logits + classifier(t-1) ----
        {
            float* sh = sm;
            *(float2*)(sh + tid * 2) = *(const float2*)(h2cur + (size_t)b2 * Hh + tid * 2);
            __syncthreads();
            int th = (bi & 1) * 64;
#pragma unroll
            for (int ii = 0; ii < 4; ii++) {
                int tp = th + ii * 16 + warp;
                const float* pr = g_proj + ((size_t)b2 * Tt + tp) * Hh;
                float s = 0.f;
#pragma unroll 8
                for (int k = lane; k < Hh; k += 32) s += sh[k] * pr[k];
                s = wred(s);
                if (lane == 0) g_logits[b2 * Tt + tp] = s * 0.03125f;
            }
            if (t > 0 && warp < 11) {
                int c = (bi & 1) * 11 + warp;
                const float* w = Wc + (size_t)c * Hh;
                float s = 0.f;
#pragma unroll 8
                for (int k = lane; k < Hh; k += 32) s += sh[k] * w[k];
                s = wred(s);
                if (lane == 0)
                    scores[((size_t)b2 * Tt + (t - 1)) * Cc + c] = s + bc[c];
            }
        }
        gbar();

        // ---- B: softmax + attn context (writes bf16 hi/lo) ----
        {
            float* sl = sm;
            float* red = sm + 128;
            if (tid < 128) { float v = g_logits[b2 * Tt + tid]; sl[tid] = v; red[tid] = v; }
            __syncthreads();
            for (int s = 64; s; s >>= 1) {
                if (tid < s) red[tid] = fmaxf(red[tid], red[tid + s]);
                __syncthreads();
            }
            float mx = red[0]; __syncthreads();
            float e = 0.f;
            if (tid < 128) { e = expf(sl[tid] - mx); red[tid] = e; }
            __syncthreads();
            for (int s = 64; s; s >>= 1) {
                if (tid < s) red[tid] += red[tid + s];
                __syncthreads();
            }
            float inv = 1.f / red[0]; __syncthreads();
            if (tid < 128) sl[tid] = e * inv;
            __syncthreads();
            if (t == Tt - 1 && (bi & 1) == 0 && tid < 128)
                aw_out[(size_t)b2 * Tt + tid] = sl[tid];

            int k = (bi & 1) * 512 + tid;
            const float* pb = g_proj + (size_t)b2 * Tt * Hh + k;
            float a = 0.f;
#pragma unroll 4
            for (int tp = 0; tp < Tt; tp++) a = fmaf(sl[tp], pb[(size_t)tp * Hh], a);
            __nv_bfloat16 ah = __float2bfloat16(a);
            g_attnhi[(size_t)b2 * Hh + k] = ah;
            g_attnlo[(size_t)b2 * Hh + k] = __float2bfloat16(a - __bfloat162float(ah));
        }
        gbar();

        // ---- C: gates = xw[t] + bf + attn@Wfused^T + h2@Whh_d^T (mma), cell ----
        {
            const __nv_bfloat16* h2hi = g_h2hi[t & 1];
            const __nv_bfloat16* h2lo = g_h2lo[t & 1];

            float acc0[4] = {0.f, 0.f, 0.f, 0.f};
            float acc1[4] = {0.f, 0.f, 0.f, 0.f};
            D_LOAD(0, 0);
            CP_COMMIT();
            for (int kc = 0; kc < 16; kc++) {
                if (kc < 15) {
                    D_LOAD((kc + 1) & 1, kc + 1);
                    CP_COMMIT();
                    CP_WAIT1();
                } else {
                    CP_WAIT0();
                }
                __syncthreads();
                uint32_t st = sb + (kc & 1) * D_STAGE;
#pragma unroll
                for (int kk = 0; kk < 4; kk++) {
                    uint32_t ka = (uint32_t)(kk * 32);
                    uint32_t ahi[4], alo[4], bhv[4], blv[4];
                    ldmx4(ahi, st + a_loff + ka);
                    ldmx4(alo, st + a_loff + D_A_PL + ka);
                    ldmx4(bhv, st + b_loff + ka);
                    ldmx4(blv, st + b_loff + D_W_PL + ka);
                    mma16816(acc0, ahi, bhv[0], bhv[2]);
                    mma16816(acc0, ahi, blv[0], blv[2]);
                    mma16816(acc0, alo, bhv[0], bhv[2]);
                    mma16816(acc1, ahi, bhv[1], bhv[3]);
                    mma16816(acc1, ahi, blv[1], blv[3]);
                    mma16816(acc1, alo, bhv[1], bhv[3]);
                }
                __syncthreads();
            }
            {   // store partials
                float* Pg = P + grp * 2048;
                int row = wm * 16 + (lane >> 2), col = wn * 16 + (lane & 3) * 2;
                Pg[row * 32 + col] = acc0[0];       Pg[row * 32 + col + 1] = acc0[1];
                Pg[(row + 8) * 32 + col] = acc0[2]; Pg[(row + 8) * 32 + col + 1] = acc0[3];
                Pg[row * 32 + col + 8] = acc1[0];       Pg[row * 32 + col + 9] = acc1[1];
                Pg[(row + 8) * 32 + col + 8] = acc1[2]; Pg[(row + 8) * 32 + col + 9] = acc1[3];
            }
            __syncthreads();
            {   // fused LSTM cell
                int b = tid >> 3, jj = tid & 7, j = bi * 8 + jj;
                float4 x4 = *(const float4*)(g_dec_xw + ((size_t)b * Tt + t) * G4 + n0 + 4 * jj);
                float4 bf4 = *(const float4*)(g_bf + n0 + 4 * jj);
                int base = b * 32 + 4 * jj;
                float vi = P[base + 0] + P[2048 + base + 0] + x4.x + bf4.x;
                float vf = P[base + 1] + P[2048 + base + 1] + x4.y + bf4.y;
                float vg = P[base + 2] + P[2048 + base + 2] + x4.z + bf4.z;
                float vo = P[base + 3] + P[2048 + base + 3] + x4.w + bf4.w;
                float cn = sigm(vf) * g_c2[b * Hh + j] + sigm(vi) * tanhf(vg);
                float hn = sigm(vo) * tanhf(cn);
                g_c2[b * Hh + j] = cn;
                g_h2f[(t + 1) & 1][b * Hh + j] = hn;
                __nv_bfloat16 hh = __float2bfloat16(hn);
                g_h2hi[(t + 1) & 1][b * Hh + j] = hh;
                g_h2lo[(t + 1) & 1][b * Hh + j] = __float2bfloat16(hn - __bfloat162float(hh));
            }
        }
        gbar();
    }

    // ---- final classifier for t = Tt-1 ----
    {
        float* sh = sm;
        *(float2*)(sh + tid * 2) = *(const float2*)(g_h2f[0] + (size_t)b2 * Hh + tid * 2);
        __syncthreads();
        if (warp < 11) {
            int c = (bi & 1) * 11 + warp;
            const float* w = Wc + (size_t)c * Hh;
            float s = 0.f;
#pragma unroll 8
            for (int k = lane; k < Hh; k += 32) s += sh[k] * w[k];
            s = wred(s);
            if (lane == 0)
                scores[((size_t)b2 * Tt + (Tt - 1)) * Cc + c] = s + bc[c];
        }
    }
#undef D_LOAD
}

// ---------------- host ----------------
extern "C" void kernel_launch(void* const* d_in, const int* in_sizes, int n_in,
                              void* d_out, int out_size)
{
    const float* x        = (const float*)d_in[0];
    const float* enc_Wih  = (const float*)d_in[1];
    const float* enc_Whh  = (const float*)d_in[2];
    const float* enc_bih  = (const float*)d_in[3];
    const float* enc_bhh  = (const float*)d_in[4];
    const float* We2d     = (const float*)d_in[5];
    const float* be2d     = (const float*)d_in[6];
    const float* Wd2e     = (const float*)d_in[7];
    const float* bd2e     = (const float*)d_in[8];
    const float* dec_Wih  = (const float*)d_in[9];
    const float* dec_Whh  = (const float*)d_in[10];
    const float* dec_bih  = (const float*)d_in[11];
    const float* dec_bhh  = (const float*)d_in[12];
    const float* Wc       = (const float*)d_in[13];
    const float* bc       = (const float*)d_in[14];

    float* out    = (float*)d_out;
    float* scores = out;
    float* aw_out = out + (size_t)Bb * Tt * Cc;

    float *enc_xw_p, *dec_xw_p, *proj_p, *Wd_h_p, *Wfused_p, *be_p, *bd_p, *zero_p;
    __nv_bfloat16 *xhi_p, *xlo_p, *Wehi_p, *Welo_p, *Wdhi_p, *Wdlo_p,
                  *htshi_p, *htslo_p, *We2dhi_p, *We2dlo_p,
                  *Whhehi_p, *Whhelo_p, *Wfhi_p, *Wflo_p, *Whhdhi_p, *Whhdlo_p,
                  *Wdhhi_p, *Wdhlo_p, *Wd2eThi_p, *Wd2eTlo_p;
    cudaGetSymbolAddress((void**)&enc_xw_p, g_enc_xw);
    cudaGetSymbolAddress((void**)&dec_xw_p, g_dec_xw);
    cudaGetSymbolAddress((void**)&proj_p,   g_proj);
    cudaGetSymbolAddress((void**)&Wd_h_p,   g_Wd_h);
    cudaGetSymbolAddress((void**)&Wfused_p, g_Wfused);
    cudaGetSymbolAddress((void**)&be_p,     g_be);
    cudaGetSymbolAddress((void**)&bd_p,     g_bd);
    cudaGetSymbolAddress((void**)&zero_p,   g_zero);
    cudaGetSymbolAddress((void**)&xhi_p,    g_xhi);
    cudaGetSymbolAddress((void**)&xlo_p,    g_xlo);
    cudaGetSymbolAddress((void**)&Wehi_p,   g_Wehi);
    cudaGetSymbolAddress((void**)&Welo_p,   g_Welo);
    cudaGetSymbolAddress((void**)&Wdhi_p,   g_Wdhi);
    cudaGetSymbolAddress((void**)&Wdlo_p,   g_Wdlo);
    cudaGetSymbolAddress((void**)&htshi_p,  g_htshi);
    cudaGetSymbolAddress((void**)&htslo_p,  g_htslo);
    cudaGetSymbolAddress((void**)&We2dhi_p, g_We2dhi);
    cudaGetSymbolAddress((void**)&We2dlo_p, g_We2dlo);
    cudaGetSymbolAddress((void**)&Whhehi_p, g_Whhehi);
    cudaGetSymbolAddress((void**)&Whhelo_p, g_Whhelo);
    cudaGetSymbolAddress((void**)&Wfhi_p,   g_Wfhi);
    cudaGetSymbolAddress((void**)&Wflo_p,   g_Wflo);
    cudaGetSymbolAddress((void**)&Whhdhi_p, g_Whhdhi);
    cudaGetSymbolAddress((void**)&Whhdlo_p, g_Whhdlo);
    cudaGetSymbolAddress((void**)&Wdhhi_p,  g_Wdhhi);
    cudaGetSymbolAddress((void**)&Wdhlo_p,  g_Wdhlo);
    cudaGetSymbolAddress((void**)&Wd2eThi_p, g_Wd2eThi);
    cudaGetSymbolAddress((void**)&Wd2eTlo_p, g_Wd2eTlo);

    cudaFuncSetAttribute(mma_gemm, cudaFuncAttributeMaxDynamicSharedMemorySize, MM_SMEM);
    cudaFuncSetAttribute(enc_scan, cudaFuncAttributeMaxDynamicSharedMemorySize, E_SMEM);
    cudaFuncSetAttribute(dec_scan, cudaFuncAttributeMaxDynamicSharedMemorySize, D_SMEM);

    // 1) zero states + barrier
    zero_kernel<<<(Bb * Hh + 255) / 256, 256>>>();

    // 2) permute weights: fused permute+split; fp32 only for Wd_h (bfused)
    perm_w_hilo_kernel<<<G4, 256>>>(Wehi_p, Welo_p, enc_Wih, Ff, Ff);
    perm_w_hilo_kernel<<<G4, 256>>>(Wdhi_p, Wdlo_p, dec_Wih, Ff + Hh, Ff);
    perm_w_hilo_kernel<<<G4, 256>>>(Whhehi_p, Whhelo_p, enc_Whh, Hh, Hh);
    perm_w_hilo_kernel<<<G4, 256>>>(Whhdhi_p, Whhdlo_p, dec_Whh, Hh, Hh);
    perm_w_hilo_kernel<<<G4, 256>>>(Wdhhi_p, Wdhlo_p, dec_Wih + Ff, Ff + Hh, Hh);
    perm_w_kernel<<<G4, 256>>>(Wd_h_p, dec_Wih + Ff, Ff + Hh, Hh);
    perm_b_kernel<<<16, 256>>>(enc_bih, enc_bhh, dec_bih, dec_bhh);
    bfused_kernel<<<G4, 32>>>(bd2e);

    // 3) remaining hi/lo conversions: x, We2d; Wd2e transposed+split
    {
        int n4 = (MT * Ff) / 4;
        conv_hilo<<<(n4 + 255) / 256, 256>>>(x, xhi_p, xlo_p, n4);
        n4 = (Hh * Hh) / 4;
        conv_hilo<<<(n4 + 255) / 256, 256>>>(We2d, We2dhi_p, We2dlo_p, n4);
        dim3 tg(32, 32);
        transp_hilo_kernel<<<tg, dim3(32, 8)>>>(Wd2e, Wd2eThi_p, Wd2eTlo_p);
    }

    // 4) Wfused = Wd_h' @ Wd2e via tensor cores, then hi/lo split
    {
        dim3 grid(Hh / 64, G4 / 128);
        mma_gemm<<<grid, 256, MM_SMEM>>>(Wdhhi_p, Wdhlo_p, Wd2eThi_p, Wd2eTlo_p,
                                         zero_p, Wfused_p, Hh, Hh);
        int n4 = (G4 * Hh) / 4;
        conv_hilo<<<(n4 + 255) / 256, 256>>>(Wfused_p, Wfhi_p, Wflo_p, n4);
    }

    // 5) tensor-core pre-GEMMs: enc_xw / dec_xw
    {
        dim3 grid(G4 / 64, MT / 128);
        mma_gemm<<<grid, 256, MM_SMEM>>>(xhi_p, xlo_p, Wehi_p, Welo_p,
                                         be_p, enc_xw_p, G4, Ff);
        mma_gemm<<<grid, 256, MM_SMEM>>>(xhi_p, xlo_p, Wdhi_p, Wdlo_p,
                                         bd_p, dec_xw_p, G4, Ff);
    }

    // 6) encoder scan
    enc_scan<<<NB, 512, E_SMEM>>>();

    // 7) tensor-core projection
    {
        dim3 grid(Hh / 64, MT / 128);
        mma_gemm<<<grid, 256, MM_SMEM>>>(htshi_p, htslo_p, We2dhi_p, We2dlo_p,
                                         be2d, proj_p, Hh, Hh);
    }

    // 8) decoder scan
    dec_scan<<<NB, 512, D_SMEM>>>(Wc, bc, scores, aw_out);
}

// round 17
// speedup vs baseline: 1.0602x; 1.0602x over previous
#include <cuda_runtime.h>
#include <cuda_bf16.h>
#include <math.h>
#include <stdint.h>

// Problem dims (fixed)
#define Bb 64
#define Tt 128
#define Ff 2048
#define Hh 1024
#define Cc 22
#define G4 4096   // 4*H
#define NB 128    // persistent grid size
#define MT 8192   // Bb*Tt

// ---------------- scratch (device globals) ----------------
__device__ float g_enc_xw[(size_t)MT*G4];
__device__ float g_dec_xw[(size_t)MT*G4];
__device__ float g_proj[(size_t)MT*Hh];
__device__ float g_c1[Bb*Hh], g_c2[Bb*Hh];
__device__ float g_h2f[2][Bb*Hh];
__device__ __nv_bfloat16 g_hhi[2][Bb*Hh], g_hlo[2][Bb*Hh];
__device__ __nv_bfloat16 g_h2hi[2][Bb*Hh], g_h2lo[2][Bb*Hh];
__device__ __nv_bfloat16 g_attnhi[Bb*Hh], g_attnlo[Bb*Hh];
__device__ float g_logits[Bb*Tt];
__device__ float g_Wd_h [(size_t)G4*Hh];
__device__ float g_Wfused[(size_t)G4*Hh];
__device__ float g_be[G4], g_bd[G4], g_bf[G4];
__device__ float g_zero[Hh];
__device__ unsigned g_barcnt, g_bargen;
// bf16 hi/lo operands
__device__ __nv_bfloat16 g_xhi[(size_t)MT*Ff],  g_xlo[(size_t)MT*Ff];
__device__ __nv_bfloat16 g_Wehi[(size_t)G4*Ff], g_Welo[(size_t)G4*Ff];
__device__ __nv_bfloat16 g_Wdhi[(size_t)G4*Ff], g_Wdlo[(size_t)G4*Ff];
__device__ __nv_bfloat16 g_htshi[(size_t)MT*Hh], g_htslo[(size_t)MT*Hh];
__device__ __nv_bfloat16 g_We2dhi[(size_t)Hh*Hh], g_We2dlo[(size_t)Hh*Hh];
__device__ __nv_bfloat16 g_Whhehi[(size_t)G4*Hh], g_Whhelo[(size_t)G4*Hh];
__device__ __nv_bfloat16 g_Wfhi[(size_t)G4*Hh],   g_Wflo[(size_t)G4*Hh];
__device__ __nv_bfloat16 g_Whhdhi[(size_t)G4*Hh], g_Whhdlo[(size_t)G4*Hh];
__device__ __nv_bfloat16 g_Wdhhi[(size_t)G4*Hh],  g_Wdhlo[(size_t)G4*Hh];
__device__ __nv_bfloat16 g_Wd2eThi[(size_t)Hh*Hh], g_Wd2eTlo[(size_t)Hh*Hh];

__device__ __forceinline__ uint32_t smem_u32(const void* p)
{
    uint32_t a;
    asm("{ .reg .u64 t; cvta.to.shared.u64 t, %1; cvt.u32.u64 %0, t; }" : "=r"(a) : "l"(p));
    return a;
}

// ---------------- mma.sync helpers ----------------
__device__ __forceinline__ void ldmx4(uint32_t* r, uint32_t addr)
{
    asm volatile("ldmatrix.sync.aligned.m8n8.x4.shared.b16 {%0,%1,%2,%3}, [%4];"
        : "=r"(r[0]), "=r"(r[1]), "=r"(r[2]), "=r"(r[3]) : "r"(addr));
}
__device__ __forceinline__ void ldmx2(uint32_t* r, uint32_t addr)
{
    asm volatile("ldmatrix.sync.aligned.m8n8.x2.shared.b16 {%0,%1}, [%2];"
        : "=r"(r[0]), "=r"(r[1]) : "r"(addr));
}
__device__ __forceinline__ void mma16816(float* c, const uint32_t* a, uint32_t b0, uint32_t b1)
{
    asm volatile(
        "mma.sync.aligned.m16n8k16.row.col.f32.bf16.bf16.f32 "
        "{%0,%1,%2,%3}, {%4,%5,%6,%7}, {%8,%9}, {%0,%1,%2,%3};"
        : "+f"(c[0]), "+f"(c[1]), "+f"(c[2]), "+f"(c[3])
        : "r"(a[0]), "r"(a[1]), "r"(a[2]), "r"(a[3]), "r"(b0), "r"(b1));
}
__device__ __forceinline__ void cpa16(uint32_t d, const void* s)
{
    asm volatile("cp.async.cg.shared.global [%0], [%1], 16;" :: "r"(d), "l"(s));
}
#define CP_COMMIT() asm volatile("cp.async.commit_group;")
#define CP_WAIT0()  asm volatile("cp.async.wait_group 0;")
#define CP_WAIT1()  asm volatile("cp.async.wait_group 1;")

// ---------------- flat grid barrier (measured-good) ----------------
__device__ __forceinline__ void gbar()
{
    __syncthreads();
    if (threadIdx.x == 0) {
        __threadfence();
        unsigned gen = *(volatile unsigned*)&g_bargen;
        if (atomicAdd(&g_barcnt, 1u) == NB - 1u) {
            g_barcnt = 0u;
            __threadfence();
            atomicAdd(&g_bargen, 1u);
        } else {
            while (*(volatile unsigned*)&g_bargen == gen) { }
        }
        __threadfence();
    }
    __syncthreads();
}

__device__ __forceinline__ float sigm(float x) { return 1.f / (1.f + expf(-x)); }
__device__ __forceinline__ float wred(float s)
{
#pragma unroll
    for (int o = 16; o; o >>= 1) s += __shfl_down_sync(0xffffffffu, s, o);
    return s;
}

// ================= setup kernels (R10, measured-good) =================
__global__ void perm_w_kernel(float* dst, const float* src, int ldsrc, int K)
{
    int r = blockIdx.x;
    int g = r >> 10, j = r & 1023;
    int p = 4 * j + g;
    const float* s = src + (size_t)r * ldsrc;
    float*       d = dst + (size_t)p * K;
    for (int k = threadIdx.x * 4; k < K; k += blockDim.x * 4)
        *(float4*)(d + k) = *(const float4*)(s + k);
}

__global__ void perm_w_hilo_kernel(__nv_bfloat16* hi, __nv_bfloat16* lo,
                                   const float* src, int ldsrc, int K)
{
    int r = blockIdx.x;
    int g = r >> 10, j = r & 1023;
    int p = 4 * j + g;
    const float* s = src + (size_t)r * ldsrc;
    __nv_bfloat16* dh = hi + (size_t)p * K;
    __nv_bfloat16* dl = lo + (size_t)p * K;
    for (int k = threadIdx.x * 4; k < K; k += blockDim.x * 4) {
        float4 v = *(const float4*)(s + k);
        __nv_bfloat162 h01, h23, l01, l23;
        h01.x = __float2bfloat16(v.x); h01.y = __float2bfloat16(v.y);
        h23.x = __float2bfloat16(v.z); h23.y = __float2bfloat16(v.w);
        l01.x = __float2bfloat16(v.x - __bfloat162float(h01.x));
        l01.y = __float2bfloat16(v.y - __bfloat162float(h01.y));
        l23.x = __float2bfloat16(v.z - __bfloat162float(h23.x));
        l23.y = __float2bfloat16(v.w - __bfloat162float(h23.y));
        *(__nv_bfloat162*)(dh + k)     = h01;
        *(__nv_bfloat162*)(dh + k + 2) = h23;
        *(__nv_bfloat162*)(dl + k)     = l01;
        *(__nv_bfloat162*)(dl + k + 2) = l23;
    }
}

__global__ void transp_hilo_kernel(const float* __restrict__ src,
                                   __nv_bfloat16* __restrict__ hi,
                                   __nv_bfloat16* __restrict__ lo)
{
    __shared__ float tile[32][33];
    int bx = blockIdx.x * 32, by = blockIdx.y * 32;
    int tx = threadIdx.x, ty = threadIdx.y;
#pragma unroll
    for (int i = 0; i < 32; i += 8)
        tile[ty + i][tx] = src[(size_t)(by + ty + i) * Hh + bx + tx];
    __syncthreads();
#pragma unroll
    for (int i = 0; i < 32; i += 8) {
        float v = tile[tx][ty + i];
        __nv_bfloat16 h = __float2bfloat16(v);
        size_t o = (size_t)(bx + ty + i) * Hh + by + tx;
        hi[o] = h;
        lo[o] = __float2bfloat16(v - __bfloat162float(h));
    }
}

__global__ void perm_b_kernel(const float* ebi, const float* ebh,
                              const float* dbi, const float* dbh)
{
    int r = blockIdx.x * blockDim.x + threadIdx.x;
    if (r < G4) {
        int g = r >> 10, j = r & 1023, p = 4 * j + g;
        g_be[p] = ebi[r] + ebh[r];
        g_bd[p] = dbi[r] + dbh[r];
    }
}

__global__ void bfused_kernel(const float* __restrict__ bd2e)
{
    int p = blockIdx.x;
    const float* w = g_Wd_h + (size_t)p * Hh;
    float s = 0.f;
    for (int k = threadIdx.x; k < Hh; k += 32) s += w[k] * bd2e[k];
    s = wred(s);
    if (threadIdx.x == 0) g_bf[p] = s;
}

__global__ void zero_kernel()
{
    int i = blockIdx.x * blockDim.x + threadIdx.x;
    if (i < Bb * Hh) {
        g_c1[i] = 0.f; g_c2[i] = 0.f;
        g_h2f[0][i] = 0.f; g_h2f[1][i] = 0.f;
        __nv_bfloat16 z = __float2bfloat16(0.f);
        g_hhi[0][i] = z; g_hlo[0][i] = z;
        g_hhi[1][i] = z; g_hlo[1][i] = z;
        g_h2hi[0][i] = z; g_h2lo[0][i] = z;
        g_h2hi[1][i] = z; g_h2lo[1][i] = z;
    }
    if (i == 0) g_barcnt = 0u;
}

__global__ void conv_hilo(const float* __restrict__ in, __nv_bfloat16* __restrict__ hi,
                          __nv_bfloat16* __restrict__ lo, int n4)
{
    int i = blockIdx.x * blockDim.x + threadIdx.x;
    if (i < n4) {
        float4 v = ((const float4*)in)[i];
        __nv_bfloat162 h01, h23, l01, l23;
        h01.x = __float2bfloat16(v.x); h01.y = __float2bfloat16(v.y);
        h23.x = __float2bfloat16(v.z); h23.y = __float2bfloat16(v.w);
        l01.x = __float2bfloat16(v.x - __bfloat162float(h01.x));
        l01.y = __float2bfloat16(v.y - __bfloat162float(h01.y));
        l23.x = __float2bfloat16(v.z - __bfloat162float(h23.x));
        l23.y = __float2bfloat16(v.w - __bfloat162float(h23.y));
        ((__nv_bfloat162*)hi)[i * 2]     = h01;
        ((__nv_bfloat162*)hi)[i * 2 + 1] = h23;
        ((__nv_bfloat162*)lo)[i * 2]     = l01;
        ((__nv_bfloat162*)lo)[i * 2 + 1] = l23;
    }
}

// ================= mma.sync bf16 split-precision GEMM (R10: BK=32, 2 CTA/SM) ====
#define PADE 40
#define ST_A   (128 * PADE * 2)
#define ST_B   (64 * PADE * 2)
#define STAGE  (2 * ST_A + 2 * ST_B)
#define MM_SMEM (2 * STAGE)

__global__ __launch_bounds__(256)
void mma_gemm(const __nv_bfloat16* __restrict__ Ahi, const __nv_bfloat16* __restrict__ Alo,
              const __nv_bfloat16* __restrict__ Bhi, const __nv_bfloat16* __restrict__ Blo,
              const float* __restrict__ bias, float* __restrict__ C, int ldc, int K)
{
    extern __shared__ char smem[];
    const uint32_t sb = smem_u32(smem);
    const int tid = threadIdx.x;
    const int wid = tid >> 5, lane = tid & 31;
    const int wm = wid & 3, wn = wid >> 2;
    const int m0 = blockIdx.y * 128, n0 = blockIdx.x * 64;

    float acc[2][4][4];
#pragma unroll
    for (int i = 0; i < 2; i++)
#pragma unroll
        for (int j = 0; j < 4; j++)
#pragma unroll
            for (int q = 0; q < 4; q++) acc[i][j][q] = 0.f;

    const int arow = tid >> 2, aseg = tid & 3;
    const int brow = tid >> 2, bseg = tid & 3;
    const int S = K >> 5;
    const int lmat = lane >> 3, lr = lane & 7;
    const uint32_t a_off0 = (uint32_t)(((wm * 32 + (lmat & 1) * 8 + lr) * PADE + (lmat >> 1) * 8) * 2);
    const uint32_t b_off0 = (uint32_t)(((wn * 32 + (lmat & 1) * 8 + lr) * PADE + (lmat >> 1) * 8) * 2);

#define LOAD_STAGE(buf, kb)                                                        \
    do {                                                                           \
        uint32_t st = sb + (buf) * STAGE;                                          \
        const __nv_bfloat16* gAh = Ahi + (size_t)(m0 + arow) * K + (kb) + aseg * 8;\
        const __nv_bfloat16* gAl = Alo + (size_t)(m0 + arow) * K + (kb) + aseg * 8;\
        uint32_t dA = st + (arow * PADE + aseg * 8) * 2;                           \
        cpa16(dA, gAh);                                                            \
        cpa16(dA + ST_A, gAl);                                                     \
        cpa16(dA + 64 * PADE * 2, gAh + (size_t)64 * K);                           \
        cpa16(dA + ST_A + 64 * PADE * 2, gAl + (size_t)64 * K);                    \
        const __nv_bfloat16* gBh = Bhi + (size_t)(n0 + brow) * K + (kb) + bseg * 8;\
        const __nv_bfloat16* gBl = Blo + (size_t)(n0 + brow) * K + (kb) + bseg * 8;\
        uint32_t dB = st + 2 * ST_A + (brow * PADE + bseg * 8) * 2;                \
        cpa16(dB, gBh);                                                            \
        cpa16(dB + ST_B, gBl);                                                     \
    } while (0)

    LOAD_STAGE(0, 0);
    CP_COMMIT();

    for (int s = 0; s < S; s++) {
        if (s + 1 < S) {
            LOAD_STAGE((s + 1) & 1, (s + 1) * 32);
            CP_COMMIT();
            CP_WAIT1();
        } else {
            CP_WAIT0();
        }
        __syncthreads();

        const uint32_t st = sb + (s & 1) * STAGE;
#pragma unroll
        for (int kk = 0; kk < 2; kk++) {
            const uint32_t kadd = (uint32_t)(kk * 16 * 2);
            uint32_t ah[2][4], al[2][4];
#pragma unroll
            for (int mf = 0; mf < 2; mf++) {
                uint32_t aaddr = st + a_off0 + (uint32_t)(mf * 16 * PADE * 2) + kadd;
                ldmx4(ah[mf], aaddr);
                ldmx4(al[mf], aaddr + ST_A);
            }
            uint32_t bh[2][4], bl[2][4];
#pragma unroll
            for (int nf2 = 0; nf2 < 2; nf2++) {
                uint32_t baddr = st + 2 * ST_A + b_off0 + (uint32_t)(nf2 * 16 * PADE * 2) + kadd;
                ldmx4(bh[nf2], baddr);
                ldmx4(bl[nf2], baddr + ST_B);
            }
#pragma unroll
            for (int mf = 0; mf < 2; mf++)
#pragma unroll
                for (int nf2 = 0; nf2 < 2; nf2++) {
                    mma16816(acc[mf][nf2 * 2 + 0], ah[mf], bh[nf2][0], bh[nf2][2]);
                    mma16816(acc[mf][nf2 * 2 + 0], ah[mf], bl[nf2][0], bl[nf2][2]);
                    mma16816(acc[mf][nf2 * 2 + 0], al[mf], bh[nf2][0], bh[nf2][2]);
                    mma16816(acc[mf][nf2 * 2 + 1], ah[mf], bh[nf2][1], bh[nf2][3]);
                    mma16816(acc[mf][nf2 * 2 + 1], ah[mf], bl[nf2][1], bl[nf2][3]);
                    mma16816(acc[mf][nf2 * 2 + 1], al[mf], bh[nf2][1], bh[nf2][3]);
                }
        }
        __syncthreads();
    }

    const int mrow = m0 + wm * 32 + (lane >> 2);
    const int ncol = n0 + wn * 32 + (lane & 3) * 2;
#pragma unroll
    for (int mf = 0; mf < 2; mf++)
#pragma unroll
        for (int nf = 0; nf < 4; nf++) {
            int r = mrow + mf * 16;
            int c = ncol + nf * 8;
            float2 b2 = *(const float2*)(bias + c);
            *(float2*)(C + (size_t)r * ldc + c) =
                make_float2(acc[mf][nf][0] + b2.x, acc[mf][nf][1] + b2.y);
            *(float2*)(C + (size_t)(r + 8) * ldc + c) =
                make_float2(acc[mf][nf][2] + b2.x, acc[mf][nf][3] + b2.y);
        }
#undef LOAD_STAGE
}

// ================= persistent encoder scan (R10 verbatim) =======================
#define EKC 64
#define EPITCH 144
#define E_A_PL (64 * EPITCH)
#define E_W_PL (32 * EPITCH)
#define E_STAGE (2 * E_A_PL + 2 * E_W_PL)
#define E_SMEM  (2 * E_STAGE + 8192)

__global__ __launch_bounds__(512)
void enc_scan()
{
    extern __shared__ char smc[];
    const uint32_t sb = smem_u32(smc);
    const int tid = threadIdx.x, bi = blockIdx.x;
    const int wid = tid >> 5, lane = tid & 31;
    const int wm = wid & 3, wn = wid >> 2;
    const int n0 = bi * 32;
    const int lmat = lane >> 3, lr = lane & 7;
    const uint32_t a_loff = (uint32_t)((wm * 16 + (lmat & 1) * 8 + lr) * EPITCH + (lmat >> 1) * 16);
    const uint32_t b_loff = (uint32_t)((wn * 8 + (lane & 7)) * EPITCH + ((lane & 15) >> 3) * 16);
    float* P = (float*)(smc + 2 * E_STAGE);
    const int ar = tid >> 3, asg = tid & 7;
    const int wpl = tid >> 8, wr = (tid >> 3) & 31, wsg = tid & 7;

#define E_LOAD(bf, kc) do {                                                       \
    uint32_t st = sb + (bf) * E_STAGE;                                            \
    int kcc = (kc) * EKC;                                                         \
    cpa16(st + ar * EPITCH + asg * 16,          Ahi + ar * Hh + kcc + asg * 8);   \
    cpa16(st + E_A_PL + ar * EPITCH + asg * 16, Alo + ar * Hh + kcc + asg * 8);   \
    const __nv_bfloat16* ws = wpl ? g_Whhelo : g_Whhehi;                          \
    cpa16(st + 2 * E_A_PL + wpl * E_W_PL + wr * EPITCH + wsg * 16,                \
          ws + (size_t)(n0 + wr) * Hh + kcc + wsg * 8);                           \
} while (0)

    for (int t = 0; t < Tt; t++) {
        const __nv_bfloat16* Ahi = g_hhi[t & 1];
        const __nv_bfloat16* Alo = g_hlo[t & 1];

        float acc[4] = {0.f, 0.f, 0.f, 0.f};
        E_LOAD(0, 0);
        CP_COMMIT();
        for (int kc = 0; kc < 16; kc++) {
            if (kc < 15) {
                E_LOAD((kc + 1) & 1, kc + 1);
                CP_COMMIT();
                CP_WAIT1();
            } else {
                CP_WAIT0();
            }
            __syncthreads();
            uint32_t st = sb + (kc & 1) * E_STAGE;
#pragma unroll
            for (int kk = 0; kk < 4; kk++) {
                uint32_t ka = (uint32_t)(kk * 32);
                uint32_t ahi[4], alo[4], bh[2], bl[2];
                ldmx4(ahi, st + a_loff + ka);
                ldmx4(alo, st + E_A_PL + a_loff + ka);
                ldmx2(bh, st + 2 * E_A_PL + b_loff + ka);
                ldmx2(bl, st + 2 * E_A_PL + E_W_PL + b_loff + ka);
                mma16816(acc, ahi, bh[0], bh[1]);
                mma16816(acc, ahi, bl[0], bl[1]);
                mma16816(acc, alo, bh[0], bh[1]);
            }
            __syncthreads();
        }
        {   // store partials
            int row = wm * 16 + (lane >> 2), col = wn * 8 + (lane & 3) * 2;
            P[row * 32 + col] = acc[0];       P[row * 32 + col + 1] = acc[1];
            P[(row + 8) * 32 + col] = acc[2]; P[(row + 8) * 32 + col + 1] = acc[3];
        }
        __syncthreads();
        {   // fused LSTM cell
            int b = tid >> 3, jj = tid & 7, j = bi * 8 + jj;
            float4 x4 = *(const float4*)(g_enc_xw + ((size_t)b * Tt + t) * G4 + n0 + 4 * jj);
            int base = b * 32 + 4 * jj;
            float vi = P[base + 0] + x4.x;
            float vf = P[base + 1] + x4.y;
            float vg = P[base + 2] + x4.z;
            float vo = P[base + 3] + x4.w;
            float cn = sigm(vf) * g_c1[b * Hh + j] + sigm(vi) * tanhf(vg);
            float hn = sigm(vo) * tanhf(cn);
            g_c1[b * Hh + j] = cn;
            __nv_bfloat16 hh = __float2bfloat16(hn);
            __nv_bfloat16 hl = __float2bfloat16(hn - __bfloat162float(hh));
            g_hhi[(t + 1) & 1][b * Hh + j] = hh;
            g_hlo[(t + 1) & 1][b * Hh + j] = hl;
            g_htshi[((size_t)b * Tt + t) * Hh + j] = hh;
            g_htslo[((size_t)b * Tt + t) * Hh + j] = hl;
        }
        gbar();
    }
#undef E_LOAD
}

// ================= persistent decoder scan (R10 verbatim: 3 barriers/step) ======
#define D_A_PL (64 * EPITCH)
#define D_W_PL (32 * EPITCH)
#define D_STAGE (4 * D_A_PL + 4 * D_W_PL)
#define D_SMEM  (2 * D_STAGE + 16384)

__global__ __launch_bounds__(512)
void dec_scan(const float* __restrict__ Wc, const float* __restrict__ bc,
              float* __restrict__ scores, float* __restrict__ aw_out)
{
    extern __shared__ char smc[];
    const uint32_t sb = smem_u32(smc);
    float* sm = (float*)smc;
    const int tid = threadIdx.x, bi = blockIdx.x;
    const int wid = tid >> 5, lane = tid & 31;
    const int warp = wid;
    const int b2 = bi >> 1;
    const int n0 = bi * 32;
    const int grp = wid >> 3, wg = wid & 7;
    const int wm = wg & 3, wn = wg >> 2;
    const int lmat = lane >> 3, lr = lane & 7;
    const uint32_t a_loff = (uint32_t)((wm * 16 + (lmat & 1) * 8 + lr) * EPITCH + (lmat >> 1) * 16)
                          + (uint32_t)(grp * 2 * D_A_PL);
    const uint32_t b_loff = (uint32_t)((wn * 16 + (lmat & 1) * 8 + lr) * EPITCH + (lmat >> 1) * 16)
                          + (uint32_t)(4 * D_A_PL + grp * 2 * D_W_PL);
    float* P = (float*)(smc + 2 * D_STAGE);
    const int ar = tid >> 3, asg = tid & 7;
    const int wpl = tid >> 8, wr = (tid >> 3) & 31, wsg = tid & 7;

#define D_LOAD(bf, kc) do {                                                       \
    uint32_t st = sb + (bf) * D_STAGE;                                            \
    int kcc = (kc) * EKC;                                                         \
    cpa16(st + 0 * D_A_PL + ar * EPITCH + asg * 16, g_attnhi + ar * Hh + kcc + asg * 8); \
    cpa16(st + 1 * D_A_PL + ar * EPITCH + asg * 16, g_attnlo + ar * Hh + kcc + asg * 8); \
    cpa16(st + 2 * D_A_PL + ar * EPITCH + asg * 16, h2hi + ar * Hh + kcc + asg * 8);     \
    cpa16(st + 3 * D_A_PL + ar * EPITCH + asg * 16, h2lo + ar * Hh + kcc + asg * 8);     \
    const __nv_bfloat16* w0s = wpl ? g_Wflo : g_Wfhi;                             \
    cpa16(st + 4 * D_A_PL + wpl * D_W_PL + wr * EPITCH + wsg * 16,                \
          w0s + (size_t)(n0 + wr) * Hh + kcc + wsg * 8);                          \
    const __nv_bfloat16* w1s = wpl ? g_Whhdlo : g_Whhdhi;                         \
    cpa16(st + 4 * D_A_PL + (2 + wpl) * D_W_PL + wr * EPITCH + wsg * 16,          \
          w1s + (size_t)(n0 + wr) * Hh + kcc + wsg * 8);                          \
} while (0)

    for (int t = 0; t < Tt; t++) {
        const float* h2cur = g_h2f[t & 1];

        // ---- A: logits + classifier(t-1) ----
        {
            float* sh = sm;
            *(float2*)(sh + tid * 2) = *(const float2*)(h2cur + (size_t)b2 * Hh + tid * 2);
            __syncthreads();
            int th = (bi & 1) * 64;
#pragma unroll
            for (int ii = 0; ii < 4; ii++) {
                int tp = th + ii * 16 + warp;
                const float* pr = g_proj + ((size_t)b2 * Tt + tp) * Hh;
                float s = 0.f;
#pragma unroll 8
                for (int k = lane; k < Hh; k += 32) s += sh[k] * pr[k];
                s = wred(s);
                if (lane == 0) g_logits[b2 * Tt + tp] = s * 0.03125f;
            }
            if (t > 0 && warp < 11) {
                int c = (bi & 1) * 11 + warp;
                const float* w = Wc + (size_t)c * Hh;
                float s = 0.f;
#pragma unroll 8
                for (int k = lane; k < Hh; k += 32) s += sh[k] * w[k];
                s = wred(s);
                if (lane == 0)
                    scores[((size_t)b2 * Tt + (t - 1)) * Cc + c] = s + bc[c];
            }
        }
        gbar();

        // ---- B: softmax + attn context (writes bf16 hi/lo) ----
        {
            float* sl = sm;
            float* red = sm + 128;
            if (tid < 128) { float v = g_logits[b2 * Tt + tid]; sl[tid] = v; red[tid] = v; }
            __syncthreads();
            for (int s = 64; s; s >>= 1) {
                if (tid < s) red[tid] = fmaxf(red[tid], red[tid + s]);
                __syncthreads();
            }
            float mx = red[0]; __syncthreads();
            float e = 0.f;
            if (tid < 128) { e = expf(sl[tid] - mx); red[tid] = e; }
            __syncthreads();
            for (int s = 64; s; s >>= 1) {
                if (tid < s) red[tid] += red[tid + s];
                __syncthreads();
            }
            float inv = 1.f / red[0]; __syncthreads();
            if (tid < 128) sl[tid] = e * inv;
            __syncthreads();
            if (t == Tt - 1 && (bi & 1) == 0 && tid < 128)
                aw_out[(size_t)b2 * Tt + tid] = sl[tid];

            int k = (bi & 1) * 512 + tid;
            const float* pb = g_proj + (size_t)b2 * Tt * Hh + k;
            float a = 0.f;
#pragma unroll 4
            for (int tp = 0; tp < Tt; tp++) a = fmaf(sl[tp], pb[(size_t)tp * Hh], a);
            __nv_bfloat16 ah = __float2bfloat16(a);
            g_attnhi[(size_t)b2 * Hh + k] = ah;
            g_attnlo[(size_t)b2 * Hh + k] = __float2bfloat16(a - __bfloat162float(ah));
        }
        gbar();

        // ---- C: gates = xw[t] + bf + attn@Wfused^T + h2@Whh_d^T (mma), cell ----
        {
            const __nv_bfloat16* h2hi = g_h2hi[t & 1];
            const __nv_bfloat16* h2lo = g_h2lo[t & 1];

            float acc0[4] = {0.f, 0.f, 0.f, 0.f};
            float acc1[4] = {0.f, 0.f, 0.f, 0.f};
            D_LOAD(0, 0);
            CP_COMMIT();
            for (int kc = 0; kc < 16; kc++) {
                if (kc < 15) {
                    D_LOAD((kc + 1) & 1, kc + 1);
                    CP_COMMIT();
                    CP_WAIT1();
                } else {
                    CP_WAIT0();
                }
                __syncthreads();
                uint32_t st = sb + (kc & 1) * D_STAGE;
#pragma unroll
                for (int kk = 0; kk < 4; kk++) {
                    uint32_t ka = (uint32_t)(kk * 32);
                    uint32_t ahi[4], alo[4], bhv[4], blv[4];
                    ldmx4(ahi, st + a_loff + ka);
                    ldmx4(alo, st + a_loff + D_A_PL + ka);
                    ldmx4(bhv, st + b_loff + ka);
                    ldmx4(blv, st + b_loff + D_W_PL + ka);
                    mma16816(acc0, ahi, bhv[0], bhv[2]);
                    mma16816(acc0, ahi, blv[0], blv[2]);
                    mma16816(acc0, alo, bhv[0], bhv[2]);
                    mma16816(acc1, ahi, bhv[1], bhv[3]);
                    mma16816(acc1, ahi, blv[1], blv[3]);
                    mma16816(acc1, alo, bhv[1], bhv[3]);
                }
                __syncthreads();
            }
            {   // store partials
                float* Pg = P + grp * 2048;
                int row = wm * 16 + (lane >> 2), col = wn * 16 + (lane & 3) * 2;
                Pg[row * 32 + col] = acc0[0];       Pg[row * 32 + col + 1] = acc0[1];
                Pg[(row + 8) * 32 + col] = acc0[2]; Pg[(row + 8) * 32 + col + 1] = acc0[3];
                Pg[row * 32 + col + 8] = acc1[0];       Pg[row * 32 + col + 9] = acc1[1];
                Pg[(row + 8) * 32 + col + 8] = acc1[2]; Pg[(row + 8) * 32 + col + 9] = acc1[3];
            }
            __syncthreads();
            {   // fused LSTM cell
                int b = tid >> 3, jj = tid & 7, j = bi * 8 + jj;
                float4 x4 = *(const float4*)(g_dec_xw + ((size_t)b * Tt + t) * G4 + n0 + 4 * jj);
                float4 bf4 = *(const float4*)(g_bf + n0 + 4 * jj);
                int base = b * 32 + 4 * jj;
                float vi = P[base + 0] + P[2048 + base + 0] + x4.x + bf4.x;
                float vf = P[base + 1] + P[2048 + base + 1] + x4.y + bf4.y;
                float vg = P[base + 2] + P[2048 + base + 2] + x4.z + bf4.z;
                float vo = P[base + 3] + P[2048 + base + 3] + x4.w + bf4.w;
                float cn = sigm(vf) * g_c2[b * Hh + j] + sigm(vi) * tanhf(vg);
                float hn = sigm(vo) * tanhf(cn);
                g_c2[b * Hh + j] = cn;
                g_h2f[(t + 1) & 1][b * Hh + j] = hn;
                __nv_bfloat16 hh = __float2bfloat16(hn);
                g_h2hi[(t + 1) & 1][b * Hh + j] = hh;
                g_h2lo[(t + 1) & 1][b * Hh + j] = __float2bfloat16(hn - __bfloat162float(hh));
            }
        }
        gbar();
    }

    // ---- final classifier for t = Tt-1 ----
    {
        float* sh = sm;
        *(float2*)(sh + tid * 2) = *(const float2*)(g_h2f[0] + (size_t)b2 * Hh + tid * 2);
        __syncthreads();
        if (warp < 11) {
            int c = (bi & 1) * 11 + warp;
            const float* w = Wc + (size_t)c * Hh;
            float s = 0.f;
#pragma unroll 8
            for (int k = lane; k < Hh; k += 32) s += sh[k] * w[k];
            s = wred(s);
            if (lane == 0)
                scores[((size_t)b2 * Tt + (Tt - 1)) * Cc + c] = s + bc[c];
        }
    }
#undef D_LOAD
}

// ---------------- host ----------------
extern "C" void kernel_launch(void* const* d_in, const int* in_sizes, int n_in,
                              void* d_out, int out_size)
{
    const float* x        = (const float*)d_in[0];
    const float* enc_Wih  = (const float*)d_in[1];
    const float* enc_Whh  = (const float*)d_in[2];
    const float* enc_bih  = (const float*)d_in[3];
    const float* enc_bhh  = (const float*)d_in[4];
    const float* We2d     = (const float*)d_in[5];
    const float* be2d     = (const float*)d_in[6];
    const float* Wd2e     = (const float*)d_in[7];
    const float* bd2e     = (const float*)d_in[8];
    const float* dec_Wih  = (const float*)d_in[9];
    const float* dec_Whh  = (const float*)d_in[10];
    const float* dec_bih  = (const float*)d_in[11];
    const float* dec_bhh  = (const float*)d_in[12];
    const float* Wc       = (const float*)d_in[13];
    const float* bc       = (const float*)d_in[14];

    float* out    = (float*)d_out;
    float* scores = out;
    float* aw_out = out + (size_t)Bb * Tt * Cc;

    float *enc_xw_p, *dec_xw_p, *proj_p, *Wd_h_p, *Wfused_p, *be_p, *bd_p, *zero_p;
    __nv_bfloat16 *xhi_p, *xlo_p, *Wehi_p, *Welo_p, *Wdhi_p, *Wdlo_p,
                  *htshi_p, *htslo_p, *We2dhi_p, *We2dlo_p,
                  *Whhehi_p, *Whhelo_p, *Wfhi_p, *Wflo_p, *Whhdhi_p, *Whhdlo_p,
                  *Wdhhi_p, *Wdhlo_p, *Wd2eThi_p, *Wd2eTlo_p;
    cudaGetSymbolAddress((void**)&enc_xw_p, g_enc_xw);
    cudaGetSymbolAddress((void**)&dec_xw_p, g_dec_xw);
    cudaGetSymbolAddress((void**)&proj_p,   g_proj);
    cudaGetSymbolAddress((void**)&Wd_h_p,   g_Wd_h);
    cudaGetSymbolAddress((void**)&Wfused_p, g_Wfused);
    cudaGetSymbolAddress((void**)&be_p,     g_be);
    cudaGetSymbolAddress((void**)&bd_p,     g_bd);
    cudaGetSymbolAddress((void**)&zero_p,   g_zero);
    cudaGetSymbolAddress((void**)&xhi_p,    g_xhi);
    cudaGetSymbolAddress((void**)&xlo_p,    g_xlo);
    cudaGetSymbolAddress((void**)&Wehi_p,   g_Wehi);
    cudaGetSymbolAddress((void**)&Welo_p,   g_Welo);
    cudaGetSymbolAddress((void**)&Wdhi_p,   g_Wdhi);
    cudaGetSymbolAddress((void**)&Wdlo_p,   g_Wdlo);
    cudaGetSymbolAddress((void**)&htshi_p,  g_htshi);
    cudaGetSymbolAddress((void**)&htslo_p,  g_htslo);
    cudaGetSymbolAddress((void**)&We2dhi_p, g_We2dhi);
    cudaGetSymbolAddress((void**)&We2dlo_p, g_We2dlo);
    cudaGetSymbolAddress((void**)&Whhehi_p, g_Whhehi);
    cudaGetSymbolAddress((void**)&Whhelo_p, g_Whhelo);
    cudaGetSymbolAddress((void**)&Wfhi_p,   g_Wfhi);
    cudaGetSymbolAddress((void**)&Wflo_p,   g_Wflo);
    cudaGetSymbolAddress((void**)&Whhdhi_p, g_Whhdhi);
    cudaGetSymbolAddress((void**)&Whhdlo_p, g_Whhdlo);
    cudaGetSymbolAddress((void**)&Wdhhi_p,  g_Wdhhi);
    cudaGetSymbolAddress((void**)&Wdhlo_p,  g_Wdhlo);
    cudaGetSymbolAddress((void**)&Wd2eThi_p, g_Wd2eThi);
    cudaGetSymbolAddress((void**)&Wd2eTlo_p, g_Wd2eTlo);

    cudaFuncSetAttribute(mma_gemm, cudaFuncAttributeMaxDynamicSharedMemorySize, MM_SMEM);
    cudaFuncSetAttribute(enc_scan, cudaFuncAttributeMaxDynamicSharedMemorySize, E_SMEM);
    cudaFuncSetAttribute(dec_scan, cudaFuncAttributeMaxDynamicSharedMemorySize, D_SMEM);

    // side stream + fork/join events (created once; never destroyed — destroying
    // mid-capture is illegal and streams hold no device memory)
    static cudaStream_t s2 = nullptr;
    static cudaEvent_t  ev_fork = nullptr, ev_join = nullptr;
    if (!s2) {
        cudaStreamCreateWithFlags(&s2, cudaStreamNonBlocking);
        cudaEventCreateWithFlags(&ev_fork, cudaEventDisableTiming);
        cudaEventCreateWithFlags(&ev_join, cudaEventDisableTiming);
    }

    // 1) zero states + barrier
    zero_kernel<<<(Bb * Hh + 255) / 256, 256>>>();

    // 2) permute weights: fused permute+split; fp32 only for Wd_h (bfused)
    perm_w_hilo_kernel<<<G4, 256>>>(Wehi_p, Welo_p, enc_Wih, Ff, Ff);
    perm_w_hilo_kernel<<<G4, 256>>>(Wdhi_p, Wdlo_p, dec_Wih, Ff + Hh, Ff);
    perm_w_hilo_kernel<<<G4, 256>>>(Whhehi_p, Whhelo_p, enc_Whh, Hh, Hh);
    perm_w_hilo_kernel<<<G4, 256>>>(Whhdhi_p, Whhdlo_p, dec_Whh, Hh, Hh);
    perm_w_hilo_kernel<<<G4, 256>>>(Wdhhi_p, Wdhlo_p, dec_Wih + Ff, Ff + Hh, Hh);
    perm_w_kernel<<<G4, 256>>>(Wd_h_p, dec_Wih + Ff, Ff + Hh, Hh);
    perm_b_kernel<<<16, 256>>>(enc_bih, enc_bhh, dec_bih, dec_bhh);
    bfused_kernel<<<G4, 32>>>(bd2e);

    // 3) remaining hi/lo conversions: x, We2d; Wd2e transposed+split
    {
        int n4 = (MT * Ff) / 4;
        conv_hilo<<<(n4 + 255) / 256, 256>>>(x, xhi_p, xlo_p, n4);
        n4 = (Hh * Hh) / 4;
        conv_hilo<<<(n4 + 255) / 256, 256>>>(We2d, We2dhi_p, We2dlo_p, n4);
        dim3 tg(32, 32);
        transp_hilo_kernel<<<tg, dim3(32, 8)>>>(Wd2e, Wd2eThi_p, Wd2eTlo_p);
    }

    // 4) fork: decoder-only work (Wfused chain + dec_xw) runs on s2,
    //    overlapping with enc_xw GEMM + encoder scan + projection on main.
    cudaEventRecord(ev_fork, 0);
    cudaStreamWaitEvent(s2, ev_fork, 0);
    {
        dim3 gridF(Hh / 64, G4 / 128);
        mma_gemm<<<gridF, 256, MM_SMEM, s2>>>(Wdhhi_p, Wdhlo_p, Wd2eThi_p, Wd2eTlo_p,
                                              zero_p, Wfused_p, Hh, Hh);
        int n4 = (G4 * Hh) / 4;
        conv_hilo<<<(n4 + 255) / 256, 256, 0, s2>>>(Wfused_p, Wfhi_p, Wflo_p, n4);
        dim3 gridP(G4 / 64, MT / 128);
        mma_gemm<<<gridP, 256, MM_SMEM, s2>>>(xhi_p, xlo_p, Wdhi_p, Wdlo_p,
                                              bd_p, dec_xw_p, G4, Ff);
    }

    // 5) main: enc_xw pre-GEMM, encoder scan, projection
    {
        dim3 gridP(G4 / 64, MT / 128);
        mma_gemm<<<gridP, 256, MM_SMEM>>>(xhi_p, xlo_p, Wehi_p, Welo_p,
                                          be_p, enc_xw_p, G4, Ff);
    }
    enc_scan<<<NB, 512, E_SMEM>>>();
    {
        dim3 gridJ(Hh / 64, MT / 128);
        mma_gemm<<<gridJ, 256, MM_SMEM>>>(htshi_p, htslo_p, We2dhi_p, We2dlo_p,
                                          be2d, proj_p, Hh, Hh);
    }

    // 6) join: dec_scan needs dec_xw + Wf hi/lo from s2
    cudaEventRecord(ev_join, s2);
    cudaStreamWaitEvent(0, ev_join, 0);

    // 7) decoder scan
    dec_scan<<<NB, 512, D_SMEM>>>(Wc, bc, scores, aw_out);
}